// round 12
// baseline (speedup 1.0000x reference)
#include <cuda_runtime.h>
#include <math_constants.h>
#include <cstdint>

#define B 16
#define T 32
#define WW 128
#define D 1024
#define NDBLK 64            // d-chunks for projection partials
#define DCHUNK (D / NDBLK)  // 16

#define FMA_F32X2(d, a, b, c) \
  asm("fma.rn.f32x2 %0, %1, %2, %3;" : "=l"(d) : "l"(a), "l"(b), "l"(c))
#define PACK2(out, lo, hi) \
  asm("mov.b64 %0, {%1, %2};" : "=l"(out) : "f"(lo), "f"(hi))
#define UNPACK2(lo, hi, in) \
  asm("mov.b64 {%0, %1}, %2;" : "=f"(lo), "=f"(hi) : "l"(in))

// Scratch (no device allocation allowed). .bss zero-init: masked-turn rows of
// g_cw are never written and stay exactly 0 across graph replays.
__device__ float g_part[2 * NDBLK * B * D];  // 8 MB
__device__ float g_q[2 * B * D];
__device__ float g_cw[B * T * D];
__device__ float g_ts[B * T];

// ---------------------------------------------------------------------------
// Kernel 1: partial projections q = source @ W via packed fp32x2 FMAs.
// grid = (NDBLK, 1, 2 mats) = 128 CTAs, 256 threads; W read exactly once.
// [R10/R11-measured]
// ---------------------------------------------------------------------------
__global__ __launch_bounds__(256) void proj_part_kernel(
    const float* __restrict__ src, const float* __restrict__ Wword,
    const float* __restrict__ Wturn) {
  int dblk = blockIdx.x;
  int mat = blockIdx.z;
  const float* __restrict__ Wm = mat ? Wturn : Wword;
  int c4 = threadIdx.x * 4;
  int d0 = dblk * DCHUNK;

  __shared__ uint64_t s_src2[DCHUNK][B];  // (s,s) packed, 2 KB
  if (threadIdx.x < DCHUNK * B) {  // 16*16 = 256
    int dl = threadIdx.x >> 4, bb = threadIdx.x & 15;
    float v = src[bb * D + d0 + dl];
    uint64_t p; PACK2(p, v, v);
    s_src2[dl][bb] = p;
  }
  __syncthreads();

  uint64_t accA[B], accB[B];  // (x,y) and (z,w) packed accumulators
#pragma unroll
  for (int bb = 0; bb < B; bb++) { accA[bb] = 0ull; accB[bb] = 0ull; }

#pragma unroll
  for (int dl = 0; dl < DCHUNK; dl++) {
    float4 wv = *reinterpret_cast<const float4*>(&Wm[(d0 + dl) * D + c4]);
    uint64_t wxy, wzw;
    PACK2(wxy, wv.x, wv.y);
    PACK2(wzw, wv.z, wv.w);
#pragma unroll
    for (int bb = 0; bb < B; bb++) {
      uint64_t ss = s_src2[dl][bb];
      FMA_F32X2(accA[bb], wxy, ss, accA[bb]);
      FMA_F32X2(accB[bb], wzw, ss, accB[bb]);
    }
  }

#pragma unroll
  for (int bb = 0; bb < B; bb++) {
    float x, y, z, w;
    UNPACK2(x, y, accA[bb]);
    UNPACK2(z, w, accB[bb]);
    float* outp = g_part + ((long)(mat * NDBLK + dblk) * B + bb) * D + c4;
    *reinterpret_cast<float4*>(outp) = make_float4(x, y, z, w);
  }
}

// ---------------------------------------------------------------------------
// Kernel 2: reduce NDBLK partials -> g_q[2][B][D]. grid = 128 x 256.
// [R10/R11-measured]
// ---------------------------------------------------------------------------
__global__ __launch_bounds__(256) void reduce_q_kernel() {
  int idx = blockIdx.x * 256 + threadIdx.x;  // 0..32767 over [2][16][1024]
  int mat = idx >> 14;
  int b = (idx >> 10) & 15;
  int c = idx & 1023;
  const float* bp = g_part + ((long)mat * NDBLK * B + b) * D + c;
  float s0 = 0.f, s1 = 0.f, s2 = 0.f, s3 = 0.f;
#pragma unroll
  for (int j = 0; j < NDBLK; j += 4) {
    s0 += bp[(long)(j + 0) * B * D];
    s1 += bp[(long)(j + 1) * B * D];
    s2 += bp[(long)(j + 2) * B * D];
    s3 += bp[(long)(j + 3) * B * D];
  }
  g_q[(mat * B + b) * D + c] = (s0 + s1) + (s2 + s3);
}

// ---------------------------------------------------------------------------
// Kernel 3: per-(b,t) word attention. R6 2-row/iter body, but qw moved to
// SHARED MEMORY (per-CTA constant) -> live regs ~110 -> 2 CTAs/SM. All ~264
// active CTAs co-resident in one wave; length imbalance averages across the
// 2 CTAs per SM instead of paying 2x wave-max.
// ---------------------------------------------------------------------------
__global__ __launch_bounds__(256, 2) void attn_kernel(
    const float* __restrict__ bank, const int* __restrict__ lens,
    const int* __restrict__ turns) {
  int t = blockIdx.x, b = blockIdx.y;
  if (t >= turns[b]) return;  // masked turn: contributes exactly 0 downstream
  int len = lens[b * T + t];
  int tid = threadIdx.x, wp = tid >> 5, lane = tid & 31;

  __shared__ __align__(16) float s_qw[D];  // 4 KB, per-CTA q_w for batch b
  *reinterpret_cast<float4*>(&s_qw[tid * 4]) =
      *reinterpret_cast<const float4*>(g_q + b * D + tid * 4);
  __syncthreads();

  const float* __restrict__ base = bank + (long)(b * T + t) * WW * D;

  float m = -CUDART_INF_F, ssum = 0.f;
  float4 acc[8];
#pragma unroll
  for (int j = 0; j < 8; j++) acc[j] = make_float4(0.f, 0.f, 0.f, 0.f);

  int w = wp;
#pragma unroll 1
  for (; w + 8 < len; w += 16) {  // two rows per iteration: w, w+8
    float4 r0[8], r1[8];
#pragma unroll
    for (int j = 0; j < 8; j++)
      r0[j] = *reinterpret_cast<const float4*>(base + w * D + j * 128 + lane * 4);
#pragma unroll
    for (int j = 0; j < 8; j++)
      r1[j] = *reinterpret_cast<const float4*>(base + (w + 8) * D + j * 128 + lane * 4);

    float p0 = 0.f, p1 = 0.f;
#pragma unroll
    for (int j = 0; j < 8; j++) {
      float4 q = *reinterpret_cast<const float4*>(&s_qw[j * 128 + lane * 4]);
      p0 = fmaf(q.x, r0[j].x, fmaf(q.y, r0[j].y,
           fmaf(q.z, r0[j].z, fmaf(q.w, r0[j].w, p0))));
      p1 = fmaf(q.x, r1[j].x, fmaf(q.y, r1[j].y,
           fmaf(q.z, r1[j].z, fmaf(q.w, r1[j].w, p1))));
    }
#pragma unroll
    for (int off = 16; off; off >>= 1) {
      p0 += __shfl_xor_sync(0xffffffffu, p0, off);
      p1 += __shfl_xor_sync(0xffffffffu, p1, off);
    }
    float mnew = fmaxf(m, fmaxf(p0, p1));
    float sc = __expf(m - mnew);        // 0 on first iteration (m = -inf)
    float e0 = __expf(p0 - mnew);
    float e1 = __expf(p1 - mnew);
    ssum = fmaf(ssum, sc, e0 + e1);
    m = mnew;
#pragma unroll
    for (int j = 0; j < 8; j++) {
      acc[j].x = fmaf(e1, r1[j].x, fmaf(e0, r0[j].x, acc[j].x * sc));
      acc[j].y = fmaf(e1, r1[j].y, fmaf(e0, r0[j].y, acc[j].y * sc));
      acc[j].z = fmaf(e1, r1[j].z, fmaf(e0, r0[j].z, acc[j].z * sc));
      acc[j].w = fmaf(e1, r1[j].w, fmaf(e0, r0[j].w, acc[j].w * sc));
    }
  }
  if (w < len) {  // tail row
    float4 r0[8];
#pragma unroll
    for (int j = 0; j < 8; j++)
      r0[j] = *reinterpret_cast<const float4*>(base + w * D + j * 128 + lane * 4);
    float p0 = 0.f;
#pragma unroll
    for (int j = 0; j < 8; j++) {
      float4 q = *reinterpret_cast<const float4*>(&s_qw[j * 128 + lane * 4]);
      p0 = fmaf(q.x, r0[j].x, fmaf(q.y, r0[j].y,
           fmaf(q.z, r0[j].z, fmaf(q.w, r0[j].w, p0))));
    }
#pragma unroll
    for (int off = 16; off; off >>= 1) p0 += __shfl_xor_sync(0xffffffffu, p0, off);
    float mnew = fmaxf(m, p0);
    float sc = __expf(m - mnew);
    float e0 = __expf(p0 - mnew);
    ssum = fmaf(ssum, sc, e0);
    m = mnew;
#pragma unroll
    for (int j = 0; j < 8; j++) {
      acc[j].x = fmaf(e0, r0[j].x, acc[j].x * sc);
      acc[j].y = fmaf(e0, r0[j].y, acc[j].y * sc);
      acc[j].z = fmaf(e0, r0[j].z, acc[j].z * sc);
      acc[j].w = fmaf(e0, r0[j].w, acc[j].w * sc);
    }
  }

  // ---- merge 8 warp-private (m, ssum, acc) states ----
  __shared__ float s_ms[8][2];
  __shared__ __align__(16) float s_acc[8][D];  // 32 KB
  if (lane == 0) { s_ms[wp][0] = m; s_ms[wp][1] = ssum; }
  __syncthreads();
  float M = -CUDART_INF_F;
#pragma unroll
  for (int k = 0; k < 8; k++) M = fmaxf(M, s_ms[k][0]);
  float S = 0.f;
#pragma unroll
  for (int k = 0; k < 8; k++) S += s_ms[k][1] * __expf(s_ms[k][0] - M);
  float wt = __expf(m - M);  // 0 for warps that saw no rows (m = -inf)
#pragma unroll
  for (int j = 0; j < 8; j++) {
    float4 v = make_float4(acc[j].x * wt, acc[j].y * wt, acc[j].z * wt, acc[j].w * wt);
    *reinterpret_cast<float4*>(&s_acc[wp][j * 128 + lane * 4]) = v;
  }
  __syncthreads();

  int c4 = tid * 4;
  float4 sum = make_float4(0.f, 0.f, 0.f, 0.f);
#pragma unroll
  for (int k = 0; k < 8; k++) {
    float4 v = *reinterpret_cast<const float4*>(&s_acc[k][c4]);
    sum.x += v.x; sum.y += v.y; sum.z += v.z; sum.w += v.w;
  }
  float inv = 1.f / S;
  float4 cw = make_float4(sum.x * inv, sum.y * inv, sum.z * inv, sum.w * inv);
  *reinterpret_cast<float4*>(g_cw + (b * T + t) * D + c4) = cw;

  // turn score: q_t . cw (block reduce)
  float4 qt = *reinterpret_cast<const float4*>(g_q + (B + b) * D + c4);
  float tp = fmaf(qt.x, cw.x, fmaf(qt.y, cw.y, fmaf(qt.z, cw.z, qt.w * cw.w)));
#pragma unroll
  for (int off = 16; off; off >>= 1) tp += __shfl_down_sync(0xffffffffu, tp, off);
  if (lane == 0) s_ms[wp][0] = tp;
  __syncthreads();
  if (tid == 0) {
    float v = 0.f;
#pragma unroll
    for (int k = 0; k < 8; k++) v += s_ms[k][0];
    g_ts[b * T + t] = v;
  }
}

// ---------------------------------------------------------------------------
// Kernel 4: turn softmax + combine, LOADS-FIRST [R11-measured]. grid =
// (16, B) = 256 CTAs, 256 threads. g_cw loads issue at entry, softmax
// overlaps them. Masked turns: weight exactly 0, g_cw rows exactly 0.
// ---------------------------------------------------------------------------
__global__ __launch_bounds__(256) void combine_kernel(
    const int* __restrict__ turns, float* __restrict__ out) {
  int b = blockIdx.y;
  int chunk = blockIdx.x;  // 64 cols = 16 float4
  int tid = threadIdx.x;
  int c = tid & 15;        // float4 index within chunk
  int tg = tid >> 4;       // 0..15 -> turns tg*2, tg*2+1
  int c4 = chunk * 64 + c * 4;
  int t0 = tg * 2, t1 = tg * 2 + 1;

  // Issue value loads FIRST — independent of the softmax.
  float4 v0 = *reinterpret_cast<const float4*>(g_cw + (b * T + t0) * D + c4);
  float4 v1 = *reinterpret_cast<const float4*>(g_cw + (b * T + t1) * D + c4);

  __shared__ float attw[T];
  __shared__ __align__(16) float s_red[16][64];
  if (tid < 32) {  // warp 0 softmax, overlapped with the loads above
    int nt = turns[b];
    float s = (tid < nt) ? g_ts[b * T + tid] : -CUDART_INF_F;
    float mx = s;
#pragma unroll
    for (int off = 16; off; off >>= 1)
      mx = fmaxf(mx, __shfl_xor_sync(0xffffffffu, mx, off));
    float e = (tid < nt) ? __expf(s - mx) : 0.f;
    float sm = e;
#pragma unroll
    for (int off = 16; off; off >>= 1)
      sm += __shfl_xor_sync(0xffffffffu, sm, off);
    attw[tid] = e / sm;
  }
  __syncthreads();

  float a0 = attw[t0], a1 = attw[t1];
  float4 acc;
  acc.x = fmaf(a0, v0.x, a1 * v1.x);
  acc.y = fmaf(a0, v0.y, a1 * v1.y);
  acc.z = fmaf(a0, v0.z, a1 * v1.z);
  acc.w = fmaf(a0, v0.w, a1 * v1.w);
  *reinterpret_cast<float4*>(&s_red[tg][c * 4]) = acc;
  __syncthreads();

  if (tid < 16) {  // reduce 16 turn-groups for one float4 each
    float4 o = make_float4(0.f, 0.f, 0.f, 0.f);
#pragma unroll
    for (int k = 0; k < 16; k++) {
      float4 v = *reinterpret_cast<const float4*>(&s_red[k][tid * 4]);
      o.x += v.x; o.y += v.y; o.z += v.z; o.w += v.w;
    }
    *reinterpret_cast<float4*>(out + b * D + chunk * 64 + tid * 4) = o;
  }
}

// ---------------------------------------------------------------------------
extern "C" void kernel_launch(void* const* d_in, const int* in_sizes, int n_in,
                              void* d_out, int out_size) {
  const float *src = nullptr, *bank = nullptr, *Wword = nullptr, *Wturn = nullptr;
  const int *lens = nullptr, *turns = nullptr;
  for (int i = 0; i < n_in; i++) {
    switch (in_sizes[i]) {
      case B * D:            src  = (const float*)d_in[i]; break;
      case B * T * WW * D:   bank = (const float*)d_in[i]; break;
      case B * T:            lens = (const int*)d_in[i];   break;
      case B:                turns = (const int*)d_in[i];  break;
      case D * D:
        if (!Wword) Wword = (const float*)d_in[i];
        else        Wturn = (const float*)d_in[i];
        break;
      default: break;
    }
  }
  proj_part_kernel<<<dim3(NDBLK, 1, 2), 256>>>(src, Wword, Wturn);
  reduce_q_kernel<<<128, 256>>>();
  attn_kernel<<<dim3(T, B), 256>>>(bank, lens, turns);
  combine_kernel<<<dim3(16, B), 256>>>(turns, (float*)d_out);
}

// round 13
// speedup vs baseline: 1.0574x; 1.0574x over previous
#include <cuda_runtime.h>
#include <cuda_pipeline.h>
#include <math_constants.h>
#include <cstdint>

#define B 16
#define T 32
#define WW 128
#define D 1024
#define NDBLK 64            // d-chunks for projection partials
#define DCHUNK (D / NDBLK)  // 16
#define PCOLS 512           // columns per proj CTA (2 halves)

#define FMA_F32X2(d, a, b, c) \
  asm("fma.rn.f32x2 %0, %1, %2, %3;" : "=l"(d) : "l"(a), "l"(b), "l"(c))
#define PACK2(out, lo, hi) \
  asm("mov.b64 %0, {%1, %2};" : "=l"(out) : "f"(lo), "f"(hi))
#define UNPACK2(lo, hi, in) \
  asm("mov.b64 {%0, %1}, %2;" : "=f"(lo), "=f"(hi) : "l"(in))

// Scratch (no device allocation allowed). .bss zero-init: masked-turn rows of
// g_cw are never written and stay exactly 0 across graph replays.
__device__ float g_part[2 * NDBLK * B * D];  // 8 MB
__device__ float g_q[2 * B * D];
__device__ float g_cw[B * T * D];
__device__ float g_ts[B * T];

// ---------------------------------------------------------------------------
// Kernel 1: partial projections q = source @ W, W staged through smem by
// cp.async (LDGSTS: no register destination -> MLP independent of register
// pressure). grid = (NDBLK, 2 col-halves, 2 mats) = 256 CTAs, 256 threads,
// ALL co-resident (34 KB smem, 2 CTAs/SM). Each thread: 2 output cols,
// 16-deep slice, 16 batches (acc = 16 packed f32x2 = 32 regs).
// ---------------------------------------------------------------------------
__global__ __launch_bounds__(256) void proj_part_kernel(
    const float* __restrict__ src, const float* __restrict__ Wword,
    const float* __restrict__ Wturn) {
  int dblk = blockIdx.x;
  int half = blockIdx.y;
  int mat = blockIdx.z;
  const float* __restrict__ Wm = mat ? Wturn : Wword;
  int tid = threadIdx.x;
  int c0 = half * PCOLS + tid * 2;  // global col of this thread's first col
  int d0 = dblk * DCHUNK;

  __shared__ __align__(16) float s_w[DCHUNK][PCOLS];  // 32 KB
  __shared__ uint64_t s_src2[DCHUNK][B];              // (s,s) packed, 2 KB

  // Stage the W chunk: 16 x 8B cp.async per thread, zero register pressure.
#pragma unroll
  for (int dl = 0; dl < DCHUNK; dl++)
    __pipeline_memcpy_async(&s_w[dl][tid * 2],
                            &Wm[(long)(d0 + dl) * D + c0], 8);
  __pipeline_commit();

  // Pack src while W flies.
  if (tid < DCHUNK * B) {  // 16*16 = 256
    int dl = tid >> 4, bb = tid & 15;
    float v = src[bb * D + d0 + dl];
    uint64_t p; PACK2(p, v, v);
    s_src2[dl][bb] = p;
  }
  __pipeline_wait_prior(0);
  __syncthreads();

  uint64_t acc[B];  // (col0, col1) packed per batch
#pragma unroll
  for (int bb = 0; bb < B; bb++) acc[bb] = 0ull;

#pragma unroll
  for (int dl = 0; dl < DCHUNK; dl++) {
    float2 wv = *reinterpret_cast<const float2*>(&s_w[dl][tid * 2]);
    uint64_t w01; PACK2(w01, wv.x, wv.y);
#pragma unroll
    for (int bb = 0; bb < B; bb++)
      FMA_F32X2(acc[bb], w01, s_src2[dl][bb], acc[bb]);
  }

#pragma unroll
  for (int bb = 0; bb < B; bb++) {
    float x, y;
    UNPACK2(x, y, acc[bb]);
    float* outp = g_part + ((long)(mat * NDBLK + dblk) * B + bb) * D + c0;
    *reinterpret_cast<float2*>(outp) = make_float2(x, y);
  }
}

// ---------------------------------------------------------------------------
// Kernel 2: reduce NDBLK partials -> g_q[2][B][D]. grid = 128 x 256.
// [R11-measured]
// ---------------------------------------------------------------------------
__global__ __launch_bounds__(256) void reduce_q_kernel() {
  int idx = blockIdx.x * 256 + threadIdx.x;  // 0..32767 over [2][16][1024]
  int mat = idx >> 14;
  int b = (idx >> 10) & 15;
  int c = idx & 1023;
  const float* bp = g_part + ((long)mat * NDBLK * B + b) * D + c;
  float s0 = 0.f, s1 = 0.f, s2 = 0.f, s3 = 0.f;
#pragma unroll
  for (int j = 0; j < NDBLK; j += 4) {
    s0 += bp[(long)(j + 0) * B * D];
    s1 += bp[(long)(j + 1) * B * D];
    s2 += bp[(long)(j + 2) * B * D];
    s3 += bp[(long)(j + 3) * B * D];
  }
  g_q[(mat * B + b) * D + c] = (s0 + s1) + (s2 + s3);
}

// ---------------------------------------------------------------------------
// Kernel 3: per-(b,t) word attention [R6/R11-measured, verbatim]. 256
// threads, 8 warps; warp-private online softmax, 2 rows/iter, register qw,
// no mainloop barriers, 1 CTA/SM.
// ---------------------------------------------------------------------------
__global__ __launch_bounds__(256) void attn_kernel(
    const float* __restrict__ bank, const int* __restrict__ lens,
    const int* __restrict__ turns) {
  int t = blockIdx.x, b = blockIdx.y;
  if (t >= turns[b]) return;  // masked turn: contributes exactly 0 downstream
  int len = lens[b * T + t];
  int tid = threadIdx.x, wp = tid >> 5, lane = tid & 31;

  float4 qw[8];
#pragma unroll
  for (int j = 0; j < 8; j++)
    qw[j] = *reinterpret_cast<const float4*>(g_q + b * D + j * 128 + lane * 4);

  const float* __restrict__ base = bank + (long)(b * T + t) * WW * D;

  float m = -CUDART_INF_F, ssum = 0.f;
  float4 acc[8];
#pragma unroll
  for (int j = 0; j < 8; j++) acc[j] = make_float4(0.f, 0.f, 0.f, 0.f);

  int w = wp;
#pragma unroll 1
  for (; w + 8 < len; w += 16) {  // two rows per iteration: w, w+8
    float4 r0[8], r1[8];
#pragma unroll
    for (int j = 0; j < 8; j++)
      r0[j] = *reinterpret_cast<const float4*>(base + w * D + j * 128 + lane * 4);
#pragma unroll
    for (int j = 0; j < 8; j++)
      r1[j] = *reinterpret_cast<const float4*>(base + (w + 8) * D + j * 128 + lane * 4);

    float p0 = 0.f, p1 = 0.f;
#pragma unroll
    for (int j = 0; j < 8; j++) {
      p0 = fmaf(qw[j].x, r0[j].x, fmaf(qw[j].y, r0[j].y,
           fmaf(qw[j].z, r0[j].z, fmaf(qw[j].w, r0[j].w, p0))));
      p1 = fmaf(qw[j].x, r1[j].x, fmaf(qw[j].y, r1[j].y,
           fmaf(qw[j].z, r1[j].z, fmaf(qw[j].w, r1[j].w, p1))));
    }
#pragma unroll
    for (int off = 16; off; off >>= 1) {
      p0 += __shfl_xor_sync(0xffffffffu, p0, off);
      p1 += __shfl_xor_sync(0xffffffffu, p1, off);
    }
    float mnew = fmaxf(m, fmaxf(p0, p1));
    float sc = __expf(m - mnew);        // 0 on first iteration (m = -inf)
    float e0 = __expf(p0 - mnew);
    float e1 = __expf(p1 - mnew);
    ssum = fmaf(ssum, sc, e0 + e1);
    m = mnew;
#pragma unroll
    for (int j = 0; j < 8; j++) {
      acc[j].x = fmaf(e1, r1[j].x, fmaf(e0, r0[j].x, acc[j].x * sc));
      acc[j].y = fmaf(e1, r1[j].y, fmaf(e0, r0[j].y, acc[j].y * sc));
      acc[j].z = fmaf(e1, r1[j].z, fmaf(e0, r0[j].z, acc[j].z * sc));
      acc[j].w = fmaf(e1, r1[j].w, fmaf(e0, r0[j].w, acc[j].w * sc));
    }
  }
  if (w < len) {  // tail row
    float4 r0[8];
#pragma unroll
    for (int j = 0; j < 8; j++)
      r0[j] = *reinterpret_cast<const float4*>(base + w * D + j * 128 + lane * 4);
    float p0 = 0.f;
#pragma unroll
    for (int j = 0; j < 8; j++)
      p0 = fmaf(qw[j].x, r0[j].x, fmaf(qw[j].y, r0[j].y,
           fmaf(qw[j].z, r0[j].z, fmaf(qw[j].w, r0[j].w, p0))));
#pragma unroll
    for (int off = 16; off; off >>= 1) p0 += __shfl_xor_sync(0xffffffffu, p0, off);
    float mnew = fmaxf(m, p0);
    float sc = __expf(m - mnew);
    float e0 = __expf(p0 - mnew);
    ssum = fmaf(ssum, sc, e0);
    m = mnew;
#pragma unroll
    for (int j = 0; j < 8; j++) {
      acc[j].x = fmaf(e0, r0[j].x, acc[j].x * sc);
      acc[j].y = fmaf(e0, r0[j].y, acc[j].y * sc);
      acc[j].z = fmaf(e0, r0[j].z, acc[j].z * sc);
      acc[j].w = fmaf(e0, r0[j].w, acc[j].w * sc);
    }
  }

  // ---- merge 8 warp-private (m, ssum, acc) states ----
  __shared__ float s_ms[8][2];
  __shared__ __align__(16) float s_acc[8][D];  // 32 KB
  if (lane == 0) { s_ms[wp][0] = m; s_ms[wp][1] = ssum; }
  __syncthreads();
  float M = -CUDART_INF_F;
#pragma unroll
  for (int k = 0; k < 8; k++) M = fmaxf(M, s_ms[k][0]);
  float S = 0.f;
#pragma unroll
  for (int k = 0; k < 8; k++) S += s_ms[k][1] * __expf(s_ms[k][0] - M);
  float wt = __expf(m - M);  // 0 for warps that saw no rows (m = -inf)
#pragma unroll
  for (int j = 0; j < 8; j++) {
    float4 v = make_float4(acc[j].x * wt, acc[j].y * wt, acc[j].z * wt, acc[j].w * wt);
    *reinterpret_cast<float4*>(&s_acc[wp][j * 128 + lane * 4]) = v;
  }
  __syncthreads();

  int c4 = tid * 4;
  float4 sum = make_float4(0.f, 0.f, 0.f, 0.f);
#pragma unroll
  for (int k = 0; k < 8; k++) {
    float4 v = *reinterpret_cast<const float4*>(&s_acc[k][c4]);
    sum.x += v.x; sum.y += v.y; sum.z += v.z; sum.w += v.w;
  }
  float inv = 1.f / S;
  float4 cw = make_float4(sum.x * inv, sum.y * inv, sum.z * inv, sum.w * inv);
  *reinterpret_cast<float4*>(g_cw + (b * T + t) * D + c4) = cw;

  // turn score: q_t . cw (block reduce)
  float4 qt = *reinterpret_cast<const float4*>(g_q + (B + b) * D + c4);
  float tp = fmaf(qt.x, cw.x, fmaf(qt.y, cw.y, fmaf(qt.z, cw.z, qt.w * cw.w)));
#pragma unroll
  for (int off = 16; off; off >>= 1) tp += __shfl_down_sync(0xffffffffu, tp, off);
  if (lane == 0) s_ms[wp][0] = tp;
  __syncthreads();
  if (tid == 0) {
    float v = 0.f;
#pragma unroll
    for (int k = 0; k < 8; k++) v += s_ms[k][0];
    g_ts[b * T + t] = v;
  }
}

// ---------------------------------------------------------------------------
// Kernel 4: turn softmax + combine, LOADS-FIRST [R11-measured, verbatim].
// grid = (16, B) = 256 CTAs, 256 threads. g_cw loads issue at entry, softmax
// overlaps them. Masked turns: weight exactly 0, g_cw rows exactly 0.
// ---------------------------------------------------------------------------
__global__ __launch_bounds__(256) void combine_kernel(
    const int* __restrict__ turns, float* __restrict__ out) {
  int b = blockIdx.y;
  int chunk = blockIdx.x;  // 64 cols = 16 float4
  int tid = threadIdx.x;
  int c = tid & 15;        // float4 index within chunk
  int tg = tid >> 4;       // 0..15 -> turns tg*2, tg*2+1
  int c4 = chunk * 64 + c * 4;
  int t0 = tg * 2, t1 = tg * 2 + 1;

  // Issue value loads FIRST — independent of the softmax.
  float4 v0 = *reinterpret_cast<const float4*>(g_cw + (b * T + t0) * D + c4);
  float4 v1 = *reinterpret_cast<const float4*>(g_cw + (b * T + t1) * D + c4);

  __shared__ float attw[T];
  __shared__ __align__(16) float s_red[16][64];
  if (tid < 32) {  // warp 0 softmax, overlapped with the loads above
    int nt = turns[b];
    float s = (tid < nt) ? g_ts[b * T + tid] : -CUDART_INF_F;
    float mx = s;
#pragma unroll
    for (int off = 16; off; off >>= 1)
      mx = fmaxf(mx, __shfl_xor_sync(0xffffffffu, mx, off));
    float e = (tid < nt) ? __expf(s - mx) : 0.f;
    float sm = e;
#pragma unroll
    for (int off = 16; off; off >>= 1)
      sm += __shfl_xor_sync(0xffffffffu, sm, off);
    attw[tid] = e / sm;
  }
  __syncthreads();

  float a0 = attw[t0], a1 = attw[t1];
  float4 acc;
  acc.x = fmaf(a0, v0.x, a1 * v1.x);
  acc.y = fmaf(a0, v0.y, a1 * v1.y);
  acc.z = fmaf(a0, v0.z, a1 * v1.z);
  acc.w = fmaf(a0, v0.w, a1 * v1.w);
  *reinterpret_cast<float4*>(&s_red[tg][c * 4]) = acc;
  __syncthreads();

  if (tid < 16) {  // reduce 16 turn-groups for one float4 each
    float4 o = make_float4(0.f, 0.f, 0.f, 0.f);
#pragma unroll
    for (int k = 0; k < 16; k++) {
      float4 v = *reinterpret_cast<const float4*>(&s_red[k][tid * 4]);
      o.x += v.x; o.y += v.y; o.z += v.z; o.w += v.w;
    }
    *reinterpret_cast<float4*>(out + b * D + chunk * 64 + tid * 4) = o;
  }
}

// ---------------------------------------------------------------------------
extern "C" void kernel_launch(void* const* d_in, const int* in_sizes, int n_in,
                              void* d_out, int out_size) {
  const float *src = nullptr, *bank = nullptr, *Wword = nullptr, *Wturn = nullptr;
  const int *lens = nullptr, *turns = nullptr;
  for (int i = 0; i < n_in; i++) {
    switch (in_sizes[i]) {
      case B * D:            src  = (const float*)d_in[i]; break;
      case B * T * WW * D:   bank = (const float*)d_in[i]; break;
      case B * T:            lens = (const int*)d_in[i];   break;
      case B:                turns = (const int*)d_in[i];  break;
      case D * D:
        if (!Wword) Wword = (const float*)d_in[i];
        else        Wturn = (const float*)d_in[i];
        break;
      default: break;
    }
  }
  proj_part_kernel<<<dim3(NDBLK, 2, 2), 256>>>(src, Wword, Wturn);
  reduce_q_kernel<<<128, 256>>>();
  attn_kernel<<<dim3(T, B), 256>>>(bank, lens, turns);
  combine_kernel<<<dim3(16, B), 256>>>(turns, (float*)d_out);
}